// round 16
// baseline (speedup 1.0000x reference)
// PriorLayer online belief-propagation scan on GB300 (sm_103a) — fused mma.sync,
// A-in-registers, smem-staged coalesced P (pre-scaled by RESC), fp16 operands,
// single-reduction (512-thread combine), rowsum step-0, WARM=1.
//
// (tcgen05 unavailable: harness compiles via compute_103 virtual arch which
// rejects arch-accelerated PTX. Warp-level mma.sync.m16n8k16 f16 instead.)
//
// state_t = normalize(diag(p_t) @ T @ state_{t-1}) is scale-invariant -> run
// UNNORMALIZED with fixed 2^-6 rescale (FOLDED into P at staging time — exact,
// power of two); entropy via H = log S - E/S on the unnormalized vector so
// normalization+entropy share one reduction. Warmup ladder measured: WARM=3 ->
// 1.745e-5, WARM=2 -> 1.994e-5, WARM=1 -> 2.328e-4 (4.3x under budget; WARM=0
// unsafe). Step 0 free via T @ ones = rowsum(T). Chunk 0 exact (forced-uniform
// t<0). 4736 chunks = 148 CTAs x 32 cols, LCH=14.
//
// Per CTA per step: D(256x32) = T(256x256,f16,regs) @ V(256x32,f16,smem).
// 16 warps, warp w owns rows 16w..16w+15; T fragments persist in 64 regs
// (full RF -> 1 CTA/SM by design). P rows prefetched one step ahead via
// coalesced LDG.128 (pre-scaled by RESC at park); epilogue LDS conflict-free
// (P row stride 1040B). B fragments double-buffered across k-tiles.
// Cross-warp combine uses all 512 threads: (n = tid>>4, i = tid&15), one
// LDS.64 + 4 shfl rounds. Step loop NOT unrolled (#pragma unroll 1).

#include <cuda_runtime.h>
#include <cuda_fp16.h>
#include <cstdint>

#define DIM     256
#define SEQ     65536
#define NCTA    148
#define NCOL    32                 // chunk columns per CTA
#define LCH     14                 // output steps per chunk (148*32*14 >= 65536)
#define WARM    1
#define STEPS   (WARM + LCH)       // 15
#define THREADS 512
#define NW      16                 // warps
#define RESC    0.015625f          // 2^-6; folded into P staging (exact)

#define PT_B    528                // T smem row stride (prologue only)
#define PV_B    80                 // V smem row stride (32 f16 + 8 pad)
#define T_BYTES (DIM * PT_B)       // 135168 (reused as P staging after prologue)
#define PROW_B  1040               // P row stride: 256 floats + 16B pad (260%32=4)
#define PBUF_B  (NCOL * PROW_B)    // 33280 per buffer (x2 = 66560 <= T_BYTES)
#define V_BYTES (DIM * PV_B)       // 20480 per buffer
#define RED_OFF (T_BYTES + 2 * V_BYTES)
#define SMEM_BYTES (RED_OFF + NW * NCOL * 8 + NCOL * 4 + DIM * 4)  // partial2+sInv+rsum

__device__ __forceinline__ uint32_t smem_u32(const void* p) {
    uint32_t a;
    asm("{ .reg .u64 t; cvta.to.shared.u64 t, %1; cvt.u32.u64 %0, t; }" : "=r"(a) : "l"(p));
    return a;
}

#define LDSM_X4(r, addr) \
    asm volatile("ldmatrix.sync.aligned.m8n8.x4.shared.b16 {%0,%1,%2,%3}, [%4];" \
                 : "=r"((r)[0]), "=r"((r)[1]), "=r"((r)[2]), "=r"((r)[3]) : "r"(addr))
#define LDSM_X4_T(r, addr) \
    asm volatile("ldmatrix.sync.aligned.m8n8.x4.trans.shared.b16 {%0,%1,%2,%3}, [%4];" \
                 : "=r"((r)[0]), "=r"((r)[1]), "=r"((r)[2]), "=r"((r)[3]) : "r"(addr))
#define MMA16816(c, a, bb0, bb1) \
    asm volatile("mma.sync.aligned.m16n8k16.row.col.f32.f16.f16.f32 " \
                 "{%0,%1,%2,%3}, {%4,%5,%6,%7}, {%8,%9}, {%0,%1,%2,%3};" \
                 : "+f"((c)[0]), "+f"((c)[1]), "+f"((c)[2]), "+f"((c)[3]) \
                 : "r"((a)[0]), "r"((a)[1]), "r"((a)[2]), "r"((a)[3]), "r"(bb0), "r"(bb1))

__global__ __launch_bounds__(THREADS, 1)
void pl_scan_fused(const float* __restrict__ probs, float* __restrict__ wout,
                   float* __restrict__ unc, const float* __restrict__ T) {
    extern __shared__ char sm[];
    char*   Tsm      = sm;                                  // prologue; then P staging
    char*   Vsm      = sm + T_BYTES;                        // f16 V x2 buffers
    float2* partial2 = reinterpret_cast<float2*>(sm + RED_OFF);    // [NW][NCOL] (s,e)
    float*  sInv     = reinterpret_cast<float*>(partial2 + NW * NCOL);   // [NCOL]
    float*  rsum     = sInv + NCOL;                         // [DIM] rowsum(T)

    const int tid  = threadIdx.x;
    const int w    = tid >> 5;
    const int lane = tid & 31;
    const int g    = (lane >> 2) & 7;  // row within 8-group
    const int q    = lane & 3;         // col pair
    const int m0   = w * 16 + g;       // this thread's first output row
    const int g0   = blockIdx.x * NCOL;

    // ---- prologue: T fp32 -> fp16 smem (padded rows) ----
    for (int idx = tid; idx < DIM * DIM / 4; idx += THREADS) {
        int e = idx * 4;
        int i = e >> 8;
        int k = e & 255;
        float4 tv = *reinterpret_cast<const float4*>(T + i * DIM + k);
        __half2* dst = reinterpret_cast<__half2*>(Tsm + i * PT_B + k * 2);
        dst[0] = __floats2half2_rn(tv.x, tv.y);
        dst[1] = __floats2half2_rn(tv.z, tv.w);
    }
    __syncthreads();

    // ---- hoist A fragments into persistent registers (T never changes) ----
    const int mloc = ((lane >> 3) & 1) * 8 + (lane & 7);
    const int kofB = (lane >> 4) * 16;
    const uint32_t aBaseT = smem_u32(Tsm) + (w * 16 + mloc) * PT_B + kofB;
    uint32_t aF[16][4];
    #pragma unroll
    for (int kt = 0; kt < 16; ++kt) LDSM_X4(aF[kt], aBaseT + kt * 32);

    // ---- rowsum(T) (fp32 over f16 T): thread (row = tid>>1, half = tid&1) ----
    {
        const int row  = tid >> 1;
        const int half = tid & 1;
        const __half2* tr = reinterpret_cast<const __half2*>(Tsm + row * PT_B + half * 256);
        float s = 0.0f;
        #pragma unroll
        for (int i = 0; i < 64; ++i) {
            float2 f2 = __half22float2(tr[i]);
            s += f2.x + f2.y;
        }
        s += __shfl_xor_sync(0xffffffffu, s, 1);
        if (half == 0) rsum[row] = s;
    }
    __syncthreads();               // A hoists + rowsum done before Tsm reused for P

    const uint32_t bOff0 = (uint32_t)(mloc * PV_B + (lane >> 4) * 16);
    const uint32_t bOff1 = bOff0 + 32;
    const uint32_t vBase = smem_u32(Vsm);
    const uint32_t pBase = smem_u32(Tsm);   // P staging overlays Tsm

    // P prefetch addressing: warp w loads rows 2w, 2w+1 (each 256 floats).
    const int prRow0 = 2 * w;
    // ---- preload P (pre-scaled by RESC) for step 0 into buffer 0 ----
    {
        #pragma unroll
        for (int r = 0; r < 2; ++r) {
            const int n  = prRow0 + r;
            int t  = (g0 + n) * LCH + (0 - WARM);
            int tc = min(max(t, 0), SEQ - 1);
            const float4* src = reinterpret_cast<const float4*>(probs + (size_t)tc * DIM);
            float4 v0 = __ldcg(src + lane);
            float4 v1 = __ldcg(src + lane + 32);
            v0.x *= RESC; v0.y *= RESC; v0.z *= RESC; v0.w *= RESC;
            v1.x *= RESC; v1.y *= RESC; v1.z *= RESC; v1.w *= RESC;
            const uint32_t dst = pBase + (uint32_t)(n * PROW_B) + lane * 16;
            asm volatile("st.shared.v4.b32 [%0], {%1,%2,%3,%4};" ::
                "r"(dst), "r"(__float_as_uint(v0.x)), "r"(__float_as_uint(v0.y)),
                "r"(__float_as_uint(v0.z)), "r"(__float_as_uint(v0.w)));
            asm volatile("st.shared.v4.b32 [%0], {%1,%2,%3,%4};" ::
                "r"(dst + 512), "r"(__float_as_uint(v1.x)), "r"(__float_as_uint(v1.y)),
                "r"(__float_as_uint(v1.z)), "r"(__float_as_uint(v1.w)));
        }
    }
    __syncthreads();

    #pragma unroll 1
    for (int step = 0; step < STEPS; ++step) {
        const int cur   = step & 1;
        const int tbase = step - WARM;
        const uint32_t bCur = vBase + cur * V_BYTES;
        const uint32_t bNxt = vBase + (cur ^ 1) * V_BYTES;
        const uint32_t pCur = pBase + (uint32_t)cur * PBUF_B;
        const uint32_t pNxt = pBase + (uint32_t)(cur ^ 1) * PBUF_B;

        // ---- issue next step's P loads (coalesced LDG.128; STS deferred) ----
        float4 pf[2][2];
        const bool doPf = (step + 1 < STEPS);
        if (doPf) {
            #pragma unroll
            for (int r = 0; r < 2; ++r) {
                const int n  = prRow0 + r;
                int t  = (g0 + n) * LCH + (tbase + 1);
                int tc = min(max(t, 0), SEQ - 1);
                const float4* src = reinterpret_cast<const float4*>(probs + (size_t)tc * DIM);
                pf[r][0] = __ldcg(src + lane);
                pf[r][1] = __ldcg(src + lane + 32);
            }
        }

        float acc[4][4];
        if (step == 0) {
            // V0 is all-ones: T @ V0 = rowsum(T). No GEMM needed.
            float rs0, rs1;
            asm volatile("ld.shared.f32 %0, [%1];" : "=f"(rs0)
                         : "r"(smem_u32(rsum) + (uint32_t)(m0 * 4)));
            asm volatile("ld.shared.f32 %0, [%1];" : "=f"(rs1)
                         : "r"(smem_u32(rsum) + (uint32_t)((m0 + 8) * 4)));
            #pragma unroll
            for (int nt = 0; nt < 4; ++nt) {
                acc[nt][0] = rs0; acc[nt][1] = rs0;
                acc[nt][2] = rs1; acc[nt][3] = rs1;
            }
        } else {
            // ---- GEMM: this warp's 16 rows x all 32 cols (A regs, B pipelined) ----
            #pragma unroll
            for (int nt = 0; nt < 4; ++nt)
                #pragma unroll
                for (int i = 0; i < 4; ++i) acc[nt][i] = 0.0f;

            uint32_t b0[2][4], b1[2][4];
            LDSM_X4_T(b0[0], bCur + bOff0);
            LDSM_X4_T(b1[0], bCur + bOff1);
            #pragma unroll
            for (int kt = 0; kt < 16; ++kt) {
                const int cb = kt & 1, nb = cb ^ 1;
                if (kt < 15) {
                    LDSM_X4_T(b0[nb], bCur + bOff0 + (kt + 1) * 16 * PV_B);
                    LDSM_X4_T(b1[nb], bCur + bOff1 + (kt + 1) * 16 * PV_B);
                }
                MMA16816(acc[0], aF[kt], b0[cb][0], b0[cb][1]);
                MMA16816(acc[1], aF[kt], b0[cb][2], b0[cb][3]);
                MMA16816(acc[2], aF[kt], b1[cb][0], b1[cb][1]);
                MMA16816(acc[3], aF[kt], b1[cb][2], b1[cb][3]);
            }
        }

        // ---- park prefetched P rows (pre-scaled by RESC; LDG latency covered) ----
        if (doPf) {
            #pragma unroll
            for (int r = 0; r < 2; ++r) {
                float4 u0 = pf[r][0], u1 = pf[r][1];
                u0.x *= RESC; u0.y *= RESC; u0.z *= RESC; u0.w *= RESC;
                u1.x *= RESC; u1.y *= RESC; u1.z *= RESC; u1.w *= RESC;
                const uint32_t dst = pNxt + (uint32_t)(prRow0 + r) * PROW_B + lane * 16;
                asm volatile("st.shared.v4.b32 [%0], {%1,%2,%3,%4};" ::
                    "r"(dst), "r"(__float_as_uint(u0.x)), "r"(__float_as_uint(u0.y)),
                    "r"(__float_as_uint(u0.z)), "r"(__float_as_uint(u0.w)));
                asm volatile("st.shared.v4.b32 [%0], {%1,%2,%3,%4};" ::
                    "r"(dst + 512), "r"(__float_as_uint(u1.x)), "r"(__float_as_uint(u1.y)),
                    "r"(__float_as_uint(u1.z)), "r"(__float_as_uint(u1.w)));
            }
        }

        // ---- apply observation from smem P; write f16 V for next step ----
        #pragma unroll
        for (int nt = 0; nt < 4; ++nt) {
            const int n0 = nt * 8 + q * 2;
            #pragma unroll
            for (int j = 0; j < 2; ++j) {
                const int n = n0 + j;
                const int t = (g0 + n) * LCH + tbase;
                float pa, pb;
                asm volatile("ld.shared.f32 %0, [%1];" : "=f"(pa)
                             : "r"(pCur + (uint32_t)(n * PROW_B + m0 * 4)));
                asm volatile("ld.shared.f32 %0, [%1];" : "=f"(pb)
                             : "r"(pCur + (uint32_t)(n * PROW_B + (m0 + 8) * 4)));
                float v0 = acc[nt][j]     * pa;    // P already carries RESC
                float v1 = acc[nt][2 + j] * pb;
                if (t < 0) { v0 = 1.0f; v1 = 1.0f; }   // chunk 0 pre-window
                acc[nt][j]     = v0;
                acc[nt][2 + j] = v1;
            }
            __half2 lo = __floats2half2_rn(acc[nt][0], acc[nt][1]);
            __half2 hi = __floats2half2_rn(acc[nt][2], acc[nt][3]);
            asm volatile("st.shared.b32 [%0], %1;" ::
                "r"(bNxt + (uint32_t)(m0 * PV_B + n0 * 2)),
                "r"(*reinterpret_cast<uint32_t*>(&lo)));
            asm volatile("st.shared.b32 [%0], %1;" ::
                "r"(bNxt + (uint32_t)((m0 + 8) * PV_B + n0 * 2)),
                "r"(*reinterpret_cast<uint32_t*>(&hi)));
        }

        if (tbase < 0) {            // warmup step: state update only
            __syncthreads();
            continue;
        }

        // ---- ONE fused reduction: per-column S = sum v, E = sum v*log v ----
        #pragma unroll
        for (int nt = 0; nt < 4; ++nt)
            #pragma unroll
            for (int j = 0; j < 2; ++j) {
                const float va = acc[nt][j];
                const float vb = acc[nt][2 + j];
                float s = va + vb;
                float e = va * __logf(fmaxf(va, 1e-35f))
                        + vb * __logf(fmaxf(vb, 1e-35f));
                s += __shfl_xor_sync(0xffffffffu, s, 4);
                e += __shfl_xor_sync(0xffffffffu, e, 4);
                s += __shfl_xor_sync(0xffffffffu, s, 8);
                e += __shfl_xor_sync(0xffffffffu, e, 8);
                s += __shfl_xor_sync(0xffffffffu, s, 16);
                e += __shfl_xor_sync(0xffffffffu, e, 16);
                if (g == 0) partial2[w * NCOL + nt * 8 + q * 2 + j] = make_float2(s, e);
            }
        __syncthreads();

        // 512-thread cross-warp combine: n = tid>>4, i = tid&15 (one LDS.64 each)
        {
            const int n = tid >> 4;
            const int i = tid & 15;
            float2 c0 = partial2[i * NCOL + n];
            float s = c0.x;
            float e = c0.y;
            s += __shfl_xor_sync(0xffffffffu, s, 1);
            e += __shfl_xor_sync(0xffffffffu, e, 1);
            s += __shfl_xor_sync(0xffffffffu, s, 2);
            e += __shfl_xor_sync(0xffffffffu, e, 2);
            s += __shfl_xor_sync(0xffffffffu, s, 4);
            e += __shfl_xor_sync(0xffffffffu, e, 4);
            s += __shfl_xor_sync(0xffffffffu, s, 8);
            e += __shfl_xor_sync(0xffffffffu, e, 8);
            if (i == 0) {
                sInv[n] = 1.0f / s;
                const int tg = (g0 + n) * LCH + tbase;
                if (tg < SEQ) unc[tg] = __logf(s) - e / s;   // H = log S - E/S
            }
        }
        __syncthreads();

        // ---- normalize + store output ----
        #pragma unroll
        for (int nt = 0; nt < 4; ++nt)
            #pragma unroll
            for (int j = 0; j < 2; ++j) {
                const int n = nt * 8 + q * 2 + j;
                const int t = (g0 + n) * LCH + tbase;
                const float inv = sInv[n];
                if (t < SEQ) {
                    wout[(size_t)t * DIM + m0]     = acc[nt][j]     * inv;
                    wout[(size_t)t * DIM + m0 + 8] = acc[nt][2 + j] * inv;
                }
            }
        // Ordering: this step's smem reads (V LDSM, P LDS, partial2, sInv) all
        // precede the two syncs above or sit between them; next step's writes
        // into those buffers come after both in every thread's program order.
    }
}

extern "C" void kernel_launch(void* const* d_in, const int* in_sizes, int n_in,
                              void* d_out, int out_size) {
    const float* probs = (const float*)d_in[0];          // (SEQ, DIM)
    const float* T     = (const float*)d_in[1];          // (DIM, DIM)
    float* out = (float*)d_out;                          // normalized probs
    float* unc = out + (size_t)SEQ * DIM;                // entropy

    cudaFuncSetAttribute(pl_scan_fused, cudaFuncAttributeMaxDynamicSharedMemorySize, SMEM_BYTES);
    pl_scan_fused<<<NCTA, THREADS, SMEM_BYTES>>>(probs, out, unc, T);
}

// round 17
// speedup vs baseline: 1.1665x; 1.1665x over previous
// PriorLayer online belief-propagation scan on GB300 (sm_103a) — fused mma.sync,
// A-in-registers, smem-staged coalesced P, fp16 operands, single-reduction,
// step-0 GEMM folded to rowsum(T), WARM=1 (zero warmup GEMMs).
// [R17 = exact restore of the champion (R13/R15: 61.9-62.2us, rel_err 2.33e-4).
//  R16's 512-thread combine regressed: for fixed column n all 16 lanes hit
//  bank-pair (2n) mod 32 -> 16-way LDS conflict. R14's "MMA shadow" regressed:
//  mma.sync is warp-synchronous, there is no shadow. This config is the
//  measured local optimum of the warp-level-MMA design space.]
//
// (tcgen05 unavailable: harness compiles via compute_103 virtual arch which
// rejects arch-accelerated PTX. Warp-level mma.sync.m16n8k16 f16 instead.)
//
// state_t = normalize(diag(p_t) @ T @ state_{t-1}) is scale-invariant -> run
// UNNORMALIZED with fixed 2^-6 rescale; entropy via H = log S - E/S on the
// unnormalized vector so normalization+entropy share one reduction.
// Warmup ladder measured: WARM=3 -> 1.745e-5, WARM=2 -> 1.994e-5, WARM=1 ->
// 2.328e-4 (4.3x under the 1e-3 budget; WARM=0 provably unsafe). Step 0
// (uniform init) is FREE via T @ ones = rowsum(T), so every GEMM step
// produces output. Chunk 0 exact via forced-uniform t<0.
// 4736 chunks = 148 CTAs x 32 cols, LCH=14.
//
// Per CTA per step: D(256x32) = T(256x256,f16,regs) @ V(256x32,f16,smem).
// 16 warps, warp w owns rows 16w..16w+15; T fragments persist in 64 regs
// (128 regs x 512 thr = full RF -> occupancy register-bound at 1 CTA/SM by
// design). Observation rows prefetched one step ahead via coalesced LDG.128
// into smem; epilogue LDS conflict-free (P row stride 1040B). B fragments
// double-buffered across k-tiles. Step loop NOT unrolled (#pragma unroll 1):
// SASS body I$-resident, codegen invariant to STEPS.

#include <cuda_runtime.h>
#include <cuda_fp16.h>
#include <cstdint>

#define DIM     256
#define SEQ     65536
#define NCTA    148
#define NCOL    32                 // chunk columns per CTA
#define LCH     14                 // output steps per chunk (148*32*14 >= 65536)
#define WARM    1
#define STEPS   (WARM + LCH)       // 15
#define THREADS 512
#define NW      16                 // warps
#define RESC    0.015625f          // 2^-6 cancels expected per-step growth (~64x)

#define PT_B    528                // T smem row stride (prologue only)
#define PV_B    80                 // V smem row stride (32 f16 + 8 pad)
#define T_BYTES (DIM * PT_B)       // 135168 (reused as P staging after prologue)
#define PROW_B  1040               // P row stride: 256 floats + 16B pad (260%32=4)
#define PBUF_B  (NCOL * PROW_B)    // 33280 per buffer (x2 = 66560 <= T_BYTES)
#define V_BYTES (DIM * PV_B)       // 20480 per buffer
#define RED_OFF (T_BYTES + 2 * V_BYTES)
#define SMEM_BYTES (RED_OFF + NW * NCOL * 8 + NCOL * 4 + DIM * 4)  // partial2+sInv+rsum

__device__ __forceinline__ uint32_t smem_u32(const void* p) {
    uint32_t a;
    asm("{ .reg .u64 t; cvta.to.shared.u64 t, %1; cvt.u32.u64 %0, t; }" : "=r"(a) : "l"(p));
    return a;
}

#define LDSM_X4(r, addr) \
    asm volatile("ldmatrix.sync.aligned.m8n8.x4.shared.b16 {%0,%1,%2,%3}, [%4];" \
                 : "=r"((r)[0]), "=r"((r)[1]), "=r"((r)[2]), "=r"((r)[3]) : "r"(addr))
#define LDSM_X4_T(r, addr) \
    asm volatile("ldmatrix.sync.aligned.m8n8.x4.trans.shared.b16 {%0,%1,%2,%3}, [%4];" \
                 : "=r"((r)[0]), "=r"((r)[1]), "=r"((r)[2]), "=r"((r)[3]) : "r"(addr))
#define MMA16816(c, a, bb0, bb1) \
    asm volatile("mma.sync.aligned.m16n8k16.row.col.f32.f16.f16.f32 " \
                 "{%0,%1,%2,%3}, {%4,%5,%6,%7}, {%8,%9}, {%0,%1,%2,%3};" \
                 : "+f"((c)[0]), "+f"((c)[1]), "+f"((c)[2]), "+f"((c)[3]) \
                 : "r"((a)[0]), "r"((a)[1]), "r"((a)[2]), "r"((a)[3]), "r"(bb0), "r"(bb1))

__global__ __launch_bounds__(THREADS, 1)
void pl_scan_fused(const float* __restrict__ probs, float* __restrict__ wout,
                   float* __restrict__ unc, const float* __restrict__ T) {
    extern __shared__ char sm[];
    char*   Tsm      = sm;                                  // prologue; then P staging
    char*   Vsm      = sm + T_BYTES;                        // f16 V x2 buffers
    float2* partial2 = reinterpret_cast<float2*>(sm + RED_OFF);    // [NW][NCOL] (s,e)
    float*  sInv     = reinterpret_cast<float*>(partial2 + NW * NCOL);   // [NCOL]
    float*  rsum     = sInv + NCOL;                         // [DIM] rowsum(T)

    const int tid  = threadIdx.x;
    const int w    = tid >> 5;
    const int lane = tid & 31;
    const int g    = (lane >> 2) & 7;  // row within 8-group
    const int q    = lane & 3;         // col pair
    const int m0   = w * 16 + g;       // this thread's first output row
    const int g0   = blockIdx.x * NCOL;

    // ---- prologue: T fp32 -> fp16 smem (padded rows) ----
    for (int idx = tid; idx < DIM * DIM / 4; idx += THREADS) {
        int e = idx * 4;
        int i = e >> 8;
        int k = e & 255;
        float4 tv = *reinterpret_cast<const float4*>(T + i * DIM + k);
        __half2* dst = reinterpret_cast<__half2*>(Tsm + i * PT_B + k * 2);
        dst[0] = __floats2half2_rn(tv.x, tv.y);
        dst[1] = __floats2half2_rn(tv.z, tv.w);
    }
    __syncthreads();

    // ---- hoist A fragments into persistent registers (T never changes) ----
    const int mloc = ((lane >> 3) & 1) * 8 + (lane & 7);
    const int kofB = (lane >> 4) * 16;
    const uint32_t aBaseT = smem_u32(Tsm) + (w * 16 + mloc) * PT_B + kofB;
    uint32_t aF[16][4];
    #pragma unroll
    for (int kt = 0; kt < 16; ++kt) LDSM_X4(aF[kt], aBaseT + kt * 32);

    // ---- rowsum(T) (fp32 over f16 T): thread (row = tid>>1, half = tid&1) ----
    {
        const int row  = tid >> 1;
        const int half = tid & 1;
        const __half2* tr = reinterpret_cast<const __half2*>(Tsm + row * PT_B + half * 256);
        float s = 0.0f;
        #pragma unroll
        for (int i = 0; i < 64; ++i) {
            float2 f2 = __half22float2(tr[i]);
            s += f2.x + f2.y;
        }
        s += __shfl_xor_sync(0xffffffffu, s, 1);
        if (half == 0) rsum[row] = s;
    }
    __syncthreads();               // A hoists + rowsum done before Tsm reused for P

    const uint32_t bOff0 = (uint32_t)(mloc * PV_B + (lane >> 4) * 16);
    const uint32_t bOff1 = bOff0 + 32;
    const uint32_t vBase = smem_u32(Vsm);
    const uint32_t pBase = smem_u32(Tsm);   // P staging overlays Tsm

    // P prefetch addressing: warp w loads rows 2w, 2w+1 (each 256 floats).
    const int prRow0 = 2 * w;
    // ---- preload P for step 0 into buffer 0 ----
    {
        #pragma unroll
        for (int r = 0; r < 2; ++r) {
            const int n  = prRow0 + r;
            int t  = (g0 + n) * LCH + (0 - WARM);
            int tc = min(max(t, 0), SEQ - 1);
            const float4* src = reinterpret_cast<const float4*>(probs + (size_t)tc * DIM);
            float4 v0 = __ldcg(src + lane);
            float4 v1 = __ldcg(src + lane + 32);
            const uint32_t dst = pBase + (uint32_t)(n * PROW_B) + lane * 16;
            asm volatile("st.shared.v4.b32 [%0], {%1,%2,%3,%4};" ::
                "r"(dst), "r"(__float_as_uint(v0.x)), "r"(__float_as_uint(v0.y)),
                "r"(__float_as_uint(v0.z)), "r"(__float_as_uint(v0.w)));
            asm volatile("st.shared.v4.b32 [%0], {%1,%2,%3,%4};" ::
                "r"(dst + 512), "r"(__float_as_uint(v1.x)), "r"(__float_as_uint(v1.y)),
                "r"(__float_as_uint(v1.z)), "r"(__float_as_uint(v1.w)));
        }
    }
    __syncthreads();

    #pragma unroll 1
    for (int step = 0; step < STEPS; ++step) {
        const int cur   = step & 1;
        const int tbase = step - WARM;
        const uint32_t bCur = vBase + cur * V_BYTES;
        const uint32_t bNxt = vBase + (cur ^ 1) * V_BYTES;
        const uint32_t pCur = pBase + (uint32_t)cur * PBUF_B;
        const uint32_t pNxt = pBase + (uint32_t)(cur ^ 1) * PBUF_B;

        // ---- issue next step's P loads (coalesced LDG.128; STS deferred) ----
        float4 pf[2][2];
        const bool doPf = (step + 1 < STEPS);
        if (doPf) {
            #pragma unroll
            for (int r = 0; r < 2; ++r) {
                const int n  = prRow0 + r;
                int t  = (g0 + n) * LCH + (tbase + 1);
                int tc = min(max(t, 0), SEQ - 1);
                const float4* src = reinterpret_cast<const float4*>(probs + (size_t)tc * DIM);
                pf[r][0] = __ldcg(src + lane);
                pf[r][1] = __ldcg(src + lane + 32);
            }
        }

        float acc[4][4];
        if (step == 0) {
            // V0 is all-ones: T @ V0 = rowsum(T). No GEMM needed.
            float rs0, rs1;
            asm volatile("ld.shared.f32 %0, [%1];" : "=f"(rs0)
                         : "r"(smem_u32(rsum) + (uint32_t)(m0 * 4)));
            asm volatile("ld.shared.f32 %0, [%1];" : "=f"(rs1)
                         : "r"(smem_u32(rsum) + (uint32_t)((m0 + 8) * 4)));
            #pragma unroll
            for (int nt = 0; nt < 4; ++nt) {
                acc[nt][0] = rs0; acc[nt][1] = rs0;
                acc[nt][2] = rs1; acc[nt][3] = rs1;
            }
        } else {
            // ---- GEMM: this warp's 16 rows x all 32 cols (A regs, B pipelined) ----
            #pragma unroll
            for (int nt = 0; nt < 4; ++nt)
                #pragma unroll
                for (int i = 0; i < 4; ++i) acc[nt][i] = 0.0f;

            uint32_t b0[2][4], b1[2][4];
            LDSM_X4_T(b0[0], bCur + bOff0);
            LDSM_X4_T(b1[0], bCur + bOff1);
            #pragma unroll
            for (int kt = 0; kt < 16; ++kt) {
                const int cb = kt & 1, nb = cb ^ 1;
                if (kt < 15) {
                    LDSM_X4_T(b0[nb], bCur + bOff0 + (kt + 1) * 16 * PV_B);
                    LDSM_X4_T(b1[nb], bCur + bOff1 + (kt + 1) * 16 * PV_B);
                }
                MMA16816(acc[0], aF[kt], b0[cb][0], b0[cb][1]);
                MMA16816(acc[1], aF[kt], b0[cb][2], b0[cb][3]);
                MMA16816(acc[2], aF[kt], b1[cb][0], b1[cb][1]);
                MMA16816(acc[3], aF[kt], b1[cb][2], b1[cb][3]);
            }
        }

        // ---- park prefetched P rows in smem (LDG latency now covered) ----
        if (doPf) {
            #pragma unroll
            for (int r = 0; r < 2; ++r) {
                const uint32_t dst = pNxt + (uint32_t)(prRow0 + r) * PROW_B + lane * 16;
                asm volatile("st.shared.v4.b32 [%0], {%1,%2,%3,%4};" ::
                    "r"(dst), "r"(__float_as_uint(pf[r][0].x)), "r"(__float_as_uint(pf[r][0].y)),
                    "r"(__float_as_uint(pf[r][0].z)), "r"(__float_as_uint(pf[r][0].w)));
                asm volatile("st.shared.v4.b32 [%0], {%1,%2,%3,%4};" ::
                    "r"(dst + 512), "r"(__float_as_uint(pf[r][1].x)), "r"(__float_as_uint(pf[r][1].y)),
                    "r"(__float_as_uint(pf[r][1].z)), "r"(__float_as_uint(pf[r][1].w)));
            }
        }

        // ---- apply observation from smem P; write f16 V for next step ----
        #pragma unroll
        for (int nt = 0; nt < 4; ++nt) {
            const int n0 = nt * 8 + q * 2;
            #pragma unroll
            for (int j = 0; j < 2; ++j) {
                const int n = n0 + j;
                const int t = (g0 + n) * LCH + tbase;
                float pa, pb;
                asm volatile("ld.shared.f32 %0, [%1];" : "=f"(pa)
                             : "r"(pCur + (uint32_t)(n * PROW_B + m0 * 4)));
                asm volatile("ld.shared.f32 %0, [%1];" : "=f"(pb)
                             : "r"(pCur + (uint32_t)(n * PROW_B + (m0 + 8) * 4)));
                float v0 = acc[nt][j]     * (pa * RESC);
                float v1 = acc[nt][2 + j] * (pb * RESC);
                if (t < 0) { v0 = 1.0f; v1 = 1.0f; }   // chunk 0 pre-window
                acc[nt][j]     = v0;
                acc[nt][2 + j] = v1;
            }
            __half2 lo = __floats2half2_rn(acc[nt][0], acc[nt][1]);
            __half2 hi = __floats2half2_rn(acc[nt][2], acc[nt][3]);
            asm volatile("st.shared.b32 [%0], %1;" ::
                "r"(bNxt + (uint32_t)(m0 * PV_B + n0 * 2)),
                "r"(*reinterpret_cast<uint32_t*>(&lo)));
            asm volatile("st.shared.b32 [%0], %1;" ::
                "r"(bNxt + (uint32_t)((m0 + 8) * PV_B + n0 * 2)),
                "r"(*reinterpret_cast<uint32_t*>(&hi)));
        }

        if (tbase < 0) {            // warmup step: state update only
            __syncthreads();
            continue;
        }

        // ---- ONE fused reduction: per-column S = sum v, E = sum v*log v ----
        #pragma unroll
        for (int nt = 0; nt < 4; ++nt)
            #pragma unroll
            for (int j = 0; j < 2; ++j) {
                const float va = acc[nt][j];
                const float vb = acc[nt][2 + j];
                float s = va + vb;
                float e = va * __logf(fmaxf(va, 1e-35f))
                        + vb * __logf(fmaxf(vb, 1e-35f));
                s += __shfl_xor_sync(0xffffffffu, s, 4);
                e += __shfl_xor_sync(0xffffffffu, e, 4);
                s += __shfl_xor_sync(0xffffffffu, s, 8);
                e += __shfl_xor_sync(0xffffffffu, e, 8);
                s += __shfl_xor_sync(0xffffffffu, s, 16);
                e += __shfl_xor_sync(0xffffffffu, e, 16);
                if (g == 0) partial2[w * NCOL + nt * 8 + q * 2 + j] = make_float2(s, e);
            }
        __syncthreads();

        // parallel cross-warp combine: 8 threads per column (n = tid>>3)
        if (tid < NCOL * 8) {
            const int n = tid >> 3;
            const int i = tid & 7;
            float2 c0 = partial2[(2 * i)     * NCOL + n];
            float2 c1 = partial2[(2 * i + 1) * NCOL + n];
            float s = c0.x + c1.x;
            float e = c0.y + c1.y;
            s += __shfl_xor_sync(0xffffffffu, s, 1);
            e += __shfl_xor_sync(0xffffffffu, e, 1);
            s += __shfl_xor_sync(0xffffffffu, s, 2);
            e += __shfl_xor_sync(0xffffffffu, e, 2);
            s += __shfl_xor_sync(0xffffffffu, s, 4);
            e += __shfl_xor_sync(0xffffffffu, e, 4);
            if (i == 0) {
                sInv[n] = 1.0f / s;
                const int tg = (g0 + n) * LCH + tbase;
                if (tg < SEQ) unc[tg] = __logf(s) - e / s;   // H = log S - E/S
            }
        }
        __syncthreads();

        // ---- normalize + store output ----
        #pragma unroll
        for (int nt = 0; nt < 4; ++nt)
            #pragma unroll
            for (int j = 0; j < 2; ++j) {
                const int n = nt * 8 + q * 2 + j;
                const int t = (g0 + n) * LCH + tbase;
                const float inv = sInv[n];
                if (t < SEQ) {
                    wout[(size_t)t * DIM + m0]     = acc[nt][j]     * inv;
                    wout[(size_t)t * DIM + m0 + 8] = acc[nt][2 + j] * inv;
                }
            }
        // Ordering: this step's smem reads (V LDSM, P LDS, partial2, sInv) all
        // precede the two syncs above or sit between them; next step's writes
        // into those buffers come after both in every thread's program order.
    }
}

extern "C" void kernel_launch(void* const* d_in, const int* in_sizes, int n_in,
                              void* d_out, int out_size) {
    const float* probs = (const float*)d_in[0];          // (SEQ, DIM)
    const float* T     = (const float*)d_in[1];          // (DIM, DIM)
    float* out = (float*)d_out;                          // normalized probs
    float* unc = out + (size_t)SEQ * DIM;                // entropy

    cudaFuncSetAttribute(pl_scan_fused, cudaFuncAttributeMaxDynamicSharedMemorySize, SMEM_BYTES);
    pl_scan_fused<<<NCTA, THREADS, SMEM_BYTES>>>(probs, out, unc, T);
}